// round 15
// baseline (speedup 1.0000x reference)
#include <cuda_runtime.h>
#include <cstdint>

// ALNNLayer fused. r12 compute shape (kg{7,6} x 8b x 1d, 128 thr, LC=4, grid(50,8))
// + weights double-buffered in smem via cp.async (zero register cost, latency hidden
// structurally). Frees ~56 regs -> 4 blocks/SM (16 warps/SM).
// Shapes: X,T,M,DT: [B=64, L=200, D=64]; alpha: [K=13]; w_v,b_t: [K,L,D];
//         w_t: [K,L,D,4]; b_v: [K,1,D]; out: [B,K,D].
// Math per (b,k,l,d):
//   kern  = exp(-relu(alpha_k)*|T-4k|) = 2^(-|a*T + na|), a = relu(alpha)*log2e, na = -a*4k
//   inten = kern * relu(X)
//   lat   = relu(wt0*X + wt1*DT + wt2*inten + wt3*M + 4*b_t)
//   out[b,k,d] = relu( sum_l w_v*lat + 200*b_v[k,d] )

#define KREF 13
#define LN   200
#define DN   64
#define BN   64
#define BT   8
#define LC   4
#define NCH  (LN / LC)            // 50
#define NBT  (BN / BT)            // 8
#define BKD  (BN * KREF * DN)     // 53248
#define KT   7                    // max k's per k-group
#define WROW 384                  // floats per k row in a stage: wv[64] bt[64] wt[256]
#define NCHK (KREF * WROW / 4)    // 1248 16-byte chunks per stage

// accumulator[b][k][d] — starts zero (static init); biaszero re-zeroes after reading.
__device__ __align__(16) float g_accum[BKD];

__device__ __forceinline__ float ex2f(float x) {
    float r; asm("ex2.approx.ftz.f32 %0, %1;" : "=f"(r) : "f"(x)); return r;
}
__device__ __forceinline__ void cp16(void* dst, const void* src) {
    uint32_t d32 = (uint32_t)__cvta_generic_to_shared(dst);
    asm volatile("cp.async.cg.shared.global [%0], [%1], 16;" :: "r"(d32), "l"(src));
}
__device__ __forceinline__ void cp_commit() { asm volatile("cp.async.commit_group;"); }
__device__ __forceinline__ void cp_wait0()  { asm volatile("cp.async.wait_group 0;"); }
__device__ __forceinline__ void cp_wait1()  { asm volatile("cp.async.wait_group 1;"); }

__global__ __launch_bounds__(128, 4)
void alnn_main(const float* __restrict__ X, const float* __restrict__ T,
               const float* __restrict__ M, const float* __restrict__ DT,
               const float* __restrict__ alpha,
               const float* __restrict__ w_v, const float* __restrict__ w_t,
               const float* __restrict__ b_t)
{
    __shared__ __align__(16) float sw[2][KREF][WROW];   // weight stages
    __shared__ float s_a[KREF], s_na[KREF];             // exp constants

    const int chunk = blockIdx.x;            // 0..49
    const int btile = blockIdx.y;            // 0..7
    const int tid   = threadIdx.x;
    const int warp  = tid >> 5;              // 0..3
    const int lane  = tid & 31;
    const int kg    = warp >> 1;             // 0/1
    const int dg    = warp & 1;              // 0/1
    const int d     = dg * 32 + lane;        // 0..63
    const int kbase = kg ? 7 : 0;
    const int kcnt  = kg ? 6 : 7;
    const int b0    = btile * BT;
    const int l0    = chunk * LC;

    if (tid < KREF) {
        const float av = fmaxf(alpha[tid], 0.0f) * 1.4426950408889634f;
        s_a[tid]  = av;
        s_na[tid] = -av * (4.0f * (float)tid);
    }

    // ---- stage weights for time-step l into smem buffer st ----
    auto stage = [&](int l, int st) {
        #pragma unroll
        for (int it = 0; it < (NCHK + 127) / 128; ++it) {
            const int c = tid + it * 128;
            if (c < NCHK) {
                const int k2 = c / 96;           // 96 chunks per k row
                const int j  = c - k2 * 96;
                const size_t base = ((size_t)k2 * LN + l) * DN;
                const float* src;
                float* dst;
                if (j < 16)      { src = w_v + base + j * 4;          dst = &sw[st][k2][j * 4]; }
                else if (j < 32) { src = b_t + base + (j - 16) * 4;   dst = &sw[st][k2][64 + (j - 16) * 4]; }
                else             { src = w_t + base * 4 + (j - 32) * 4; dst = &sw[st][k2][128 + (j - 32) * 4]; }
                cp16(dst, src);
            }
        }
    };

    float acc[KT][BT];
    #pragma unroll
    for (int kk = 0; kk < KT; kk++)
        #pragma unroll
        for (int bi = 0; bi < BT; bi++) acc[kk][bi] = 0.0f;

    const size_t bstr = (size_t)LN * DN;

    stage(l0, 0);
    cp_commit();

    int st = 0;
    #pragma unroll
    for (int li = 0; li < LC; li++) {
        const int l = l0 + li;

        if (li + 1 < LC) { stage(l + 1, st ^ 1); cp_commit(); }

        // batched input loads (independent of smem; overlap the cp.async wait)
        const size_t ibase = (size_t)l * DN + d + (size_t)b0 * bstr;
        float x[BT], t[BT], m[BT], dt[BT], rx[BT];
        #pragma unroll
        for (int bi = 0; bi < BT; bi++) {
            const size_t o = ibase + (size_t)bi * bstr;
            x[bi]  = __ldg(X  + o);
            t[bi]  = __ldg(T  + o);
            m[bi]  = __ldg(M  + o);
            dt[bi] = __ldg(DT + o);
        }
        #pragma unroll
        for (int bi = 0; bi < BT; bi++) rx[bi] = fmaxf(x[bi], 0.0f);

        if (li + 1 < LC) cp_wait1(); else cp_wait0();   // stage st complete
        __syncthreads();

        // ---- compute from smem weights ----
        #pragma unroll
        for (int kk = 0; kk < KT; kk++) {
            if (kk < kcnt) {
                const int k = kbase + kk;
                const float ak  = s_a[k];
                const float nak = s_na[k];
                const float wvk = sw[st][k][d];
                const float btk = 4.0f * sw[st][k][64 + d];
                const float4 w  = *reinterpret_cast<const float4*>(&sw[st][k][128 + 4 * d]);

                #pragma unroll
                for (int bi = 0; bi < BT; bi++) {
                    const float ww = fmaf(t[bi], ak, nak);
                    const float e  = ex2f(-fabsf(ww));       // 2^(-|w|)
                    const float in = e * rx[bi];
                    const float s  = fmaf(w.x, x[bi],
                                     fmaf(w.y, dt[bi],
                                     fmaf(w.z, in,
                                     fmaf(w.w, m[bi], btk))));
                    acc[kk][bi] = fmaf(wvk, fmaxf(s, 0.0f), acc[kk][bi]);
                }
            }
        }

        __syncthreads();          // all reads of stage st done before re-staging
        st ^= 1;
    }

    // coalesced fp32 reductions into the L2-resident accumulator
    #pragma unroll
    for (int kk = 0; kk < KT; kk++) {
        if (kk < kcnt) {
            #pragma unroll
            for (int bi = 0; bi < BT; bi++) {
                atomicAdd(&g_accum[((size_t)(b0 + bi) * KREF + (kbase + kk)) * DN + d],
                          acc[kk][bi]);
            }
        }
    }
}

// bias + relu epilogue; one scalar per thread (208 blocks). Re-zeroes accumulator.
__global__ __launch_bounds__(256)
void alnn_biaszero(const float* __restrict__ b_v, float* __restrict__ out)
{
    const int g = blockIdx.x * 256 + threadIdx.x;   // over BKD = 53248
    if (g >= BKD) return;
    const int d  = g & 63;
    const int k  = (g >> 6) % KREF;

    const float s  = g_accum[g];
    const float bv = __ldg(b_v + k * DN + d);
    out[g] = fmaxf(fmaf(200.f, bv, s), 0.f);
    g_accum[g] = 0.f;                               // ready for next call
}

extern "C" void kernel_launch(void* const* d_in, const int* in_sizes, int n_in,
                              void* d_out, int out_size)
{
    // metadata order: X, T, M, DT, alpha, w_v, w_t, b_v, b_t
    const float* X     = (const float*)d_in[0];
    const float* T     = (const float*)d_in[1];
    const float* M     = (const float*)d_in[2];
    const float* DT    = (const float*)d_in[3];
    const float* alpha = (const float*)d_in[4];
    const float* w_v   = (const float*)d_in[5];
    const float* w_t   = (const float*)d_in[6];
    const float* b_v   = (const float*)d_in[7];
    const float* b_t   = (const float*)d_in[8];
    float* out = (float*)d_out;

    dim3 grid(NCH, NBT);
    alnn_main<<<grid, 128>>>(X, T, M, DT, alpha, w_v, w_t, b_t);
    alnn_biaszero<<<(BKD + 255) / 256, 256>>>(b_v, out);
}

// round 16
// speedup vs baseline: 1.4343x; 1.4343x over previous
#include <cuda_runtime.h>
#include <cstdint>

// ALNNLayer fused. r12 structure with BT=4: thread = (k-group {7,6}) x (4 b) x (1 d),
// 128 thr, LC=4, grid (50, 16) = 800 blocks, ~105 regs -> 4 blocks/SM (16 warps/SM).
// Per-l-step loads batched up-front (r12 win). L-reduction via coalesced fp32
// atomicAdd into a 213KB L2-resident accumulator; separate bias+relu epilogue.
// Shapes: X,T,M,DT: [B=64, L=200, D=64]; alpha: [K=13]; w_v,b_t: [K,L,D];
//         w_t: [K,L,D,4]; b_v: [K,1,D]; out: [B,K,D].
// Math per (b,k,l,d):
//   kern  = exp(-relu(alpha_k)*|T-4k|) = 2^(-|a*T + na|), a = relu(alpha)*log2e, na = -a*4k
//   inten = kern * relu(X)
//   lat   = relu(wt0*X + wt1*DT + wt2*inten + wt3*M + 4*b_t)
//   out[b,k,d] = relu( sum_l w_v*lat + 200*b_v[k,d] )

#define KREF 13
#define LN   200
#define DN   64
#define BN   64
#define BT   4
#define LC   4
#define NCH  (LN / LC)          // 50
#define NBT  (BN / BT)          // 16
#define BKD  (BN * KREF * DN)   // 53248
#define KT   7                  // max k's per k-group

// accumulator[b][k][d] — starts zero (static init); biaszero re-zeroes after reading.
__device__ __align__(16) float g_accum[BKD];

__device__ __forceinline__ float ex2f(float x) {
    float r; asm("ex2.approx.ftz.f32 %0, %1;" : "=f"(r) : "f"(x)); return r;
}

__global__ __launch_bounds__(128, 4)
void alnn_main(const float* __restrict__ X, const float* __restrict__ T,
               const float* __restrict__ M, const float* __restrict__ DT,
               const float* __restrict__ alpha,
               const float* __restrict__ w_v, const float* __restrict__ w_t,
               const float* __restrict__ b_t)
{
    const int chunk = blockIdx.x;            // 0..49
    const int btile = blockIdx.y;            // 0..15
    const int warp  = threadIdx.x >> 5;      // 0..3
    const int lane  = threadIdx.x & 31;
    const int kg    = warp >> 1;             // 0/1
    const int dg    = warp & 1;              // 0/1
    const int d     = dg * 32 + lane;        // 0..63
    const int kbase = kg ? 7 : 0;
    const int kcnt  = kg ? 6 : 7;
    const int b0    = btile * BT;
    const int l0    = chunk * LC;

    // per-k exp constants
    float a[KT], na[KT];
    #pragma unroll
    for (int kk = 0; kk < KT; kk++) {
        if (kk < kcnt) {
            const int k = kbase + kk;
            const float av = fmaxf(__ldg(alpha + k), 0.0f) * 1.4426950408889634f;
            a[kk]  = av;
            na[kk] = -av * (4.0f * (float)k);
        } else { a[kk] = 0.0f; na[kk] = 0.0f; }
    }

    float acc[KT][BT];
    #pragma unroll
    for (int kk = 0; kk < KT; kk++)
        #pragma unroll
        for (int bi = 0; bi < BT; bi++) acc[kk][bi] = 0.0f;

    const size_t bstr = (size_t)LN * DN;

    #pragma unroll
    for (int li = 0; li < LC; li++) {
        const int l = l0 + li;

        // ---- batch ALL loads for this l-step first (max MLP, one latency hole) ----
        float  wv[KT], bt4[KT];
        float4 wt[KT];
        #pragma unroll
        for (int kk = 0; kk < KT; kk++) {
            if (kk < kcnt) {
                const size_t woff = ((size_t)(kbase + kk) * LN + l) * DN + d;
                wv[kk]  = __ldg(w_v + woff);
                bt4[kk] = __ldg(b_t + woff);
                wt[kk]  = __ldg(reinterpret_cast<const float4*>(w_t) + woff);
            }
        }

        const size_t ibase = (size_t)l * DN + d + (size_t)b0 * bstr;
        float x[BT], t[BT], m[BT], dt[BT], rx[BT];
        #pragma unroll
        for (int bi = 0; bi < BT; bi++) {
            const size_t o = ibase + (size_t)bi * bstr;
            x[bi]  = __ldg(X  + o);
            t[bi]  = __ldg(T  + o);
            m[bi]  = __ldg(M  + o);
            dt[bi] = __ldg(DT + o);
        }

        #pragma unroll
        for (int bi = 0; bi < BT; bi++) rx[bi] = fmaxf(x[bi], 0.0f);
        #pragma unroll
        for (int kk = 0; kk < KT; kk++)
            if (kk < kcnt) bt4[kk] *= 4.0f;

        // ---- compute ----
        #pragma unroll
        for (int kk = 0; kk < KT; kk++) {
            if (kk < kcnt) {
                const float ak = a[kk], nak = na[kk];
                const float4 w = wt[kk];
                const float wvk = wv[kk], btk = bt4[kk];

                #pragma unroll
                for (int bi = 0; bi < BT; bi++) {
                    const float ww = fmaf(t[bi], ak, nak);
                    const float e  = ex2f(-fabsf(ww));       // 2^(-|w|)
                    const float in = e * rx[bi];
                    const float s  = fmaf(w.x, x[bi],
                                     fmaf(w.y, dt[bi],
                                     fmaf(w.z, in,
                                     fmaf(w.w, m[bi], btk))));
                    acc[kk][bi] = fmaf(wvk, fmaxf(s, 0.0f), acc[kk][bi]);
                }
            }
        }
    }

    // coalesced fp32 reductions into the L2-resident accumulator
    #pragma unroll
    for (int kk = 0; kk < KT; kk++) {
        if (kk < kcnt) {
            #pragma unroll
            for (int bi = 0; bi < BT; bi++) {
                atomicAdd(&g_accum[((size_t)(b0 + bi) * KREF + (kbase + kk)) * DN + d],
                          acc[kk][bi]);
            }
        }
    }
}

// bias + relu epilogue; one scalar per thread (208 blocks). Re-zeroes accumulator.
__global__ __launch_bounds__(256)
void alnn_biaszero(const float* __restrict__ b_v, float* __restrict__ out)
{
    const int g = blockIdx.x * 256 + threadIdx.x;   // over BKD = 53248
    if (g >= BKD) return;
    const int d  = g & 63;
    const int k  = (g >> 6) % KREF;

    const float s  = g_accum[g];
    const float bv = __ldg(b_v + k * DN + d);
    out[g] = fmaxf(fmaf(200.f, bv, s), 0.f);
    g_accum[g] = 0.f;                               // ready for next call
}

extern "C" void kernel_launch(void* const* d_in, const int* in_sizes, int n_in,
                              void* d_out, int out_size)
{
    // metadata order: X, T, M, DT, alpha, w_v, w_t, b_v, b_t
    const float* X     = (const float*)d_in[0];
    const float* T     = (const float*)d_in[1];
    const float* M     = (const float*)d_in[2];
    const float* DT    = (const float*)d_in[3];
    const float* alpha = (const float*)d_in[4];
    const float* w_v   = (const float*)d_in[5];
    const float* w_t   = (const float*)d_in[6];
    const float* b_v   = (const float*)d_in[7];
    const float* b_t   = (const float*)d_in[8];
    float* out = (float*)d_out;

    dim3 grid(NCH, NBT);
    alnn_main<<<grid, 128>>>(X, T, M, DT, alpha, w_v, w_t, b_t);
    alnn_biaszero<<<(BKD + 255) / 256, 256>>>(b_v, out);
}

// round 17
// speedup vs baseline: 1.5287x; 1.0658x over previous
#include <cuda_runtime.h>
#include <cstdint>

// ALNNLayer fused. Software-pipelined register double-buffering: inputs + wv + b_t for
// step l+1 are loaded BEFORE computing step l (hides the L1tex wavefront-queue delay
// under compute). wt float4 batch single-buffered at top of compute. thread =
// (k-group {7,6}) x (4 b) x (1 d), 128 thr, LC=4, grid (50,16)=800 blocks, 3 blocks/SM.
// L-reduction via coalesced fp32 atomicAdd into a 213KB L2-resident accumulator.
// Shapes: X,T,M,DT: [B=64, L=200, D=64]; alpha: [K=13]; w_v,b_t: [K,L,D];
//         w_t: [K,L,D,4]; b_v: [K,1,D]; out: [B,K,D].
// Math per (b,k,l,d):
//   kern  = exp(-relu(alpha_k)*|T-4k|) = 2^(-|a*T + na|), a = relu(alpha)*log2e, na = -a*4k
//   inten = kern * relu(X)
//   lat   = relu(wt0*X + wt1*DT + wt2*inten + wt3*M + 4*b_t)
//   out[b,k,d] = relu( sum_l w_v*lat + 200*b_v[k,d] )

#define KREF 13
#define LN   200
#define DN   64
#define BN   64
#define BT   4
#define LC   4
#define NCH  (LN / LC)          // 50
#define NBT  (BN / BT)          // 16
#define BKD  (BN * KREF * DN)   // 53248
#define KT   7                  // max k's per k-group

// accumulator[b][k][d] — starts zero (static init); biaszero re-zeroes after reading.
__device__ __align__(16) float g_accum[BKD];

__device__ __forceinline__ float ex2f(float x) {
    float r; asm("ex2.approx.ftz.f32 %0, %1;" : "=f"(r) : "f"(x)); return r;
}

__global__ __launch_bounds__(128, 3)
void alnn_main(const float* __restrict__ X, const float* __restrict__ T,
               const float* __restrict__ M, const float* __restrict__ DT,
               const float* __restrict__ alpha,
               const float* __restrict__ w_v, const float* __restrict__ w_t,
               const float* __restrict__ b_t)
{
    const int chunk = blockIdx.x;            // 0..49
    const int btile = blockIdx.y;            // 0..15
    const int warp  = threadIdx.x >> 5;      // 0..3
    const int lane  = threadIdx.x & 31;
    const int kg    = warp >> 1;             // 0/1
    const int dg    = warp & 1;              // 0/1
    const int d     = dg * 32 + lane;        // 0..63
    const int kbase = kg ? 7 : 0;
    const int kcnt  = kg ? 6 : 7;
    const int b0    = btile * BT;
    const int l0    = chunk * LC;

    // per-k exp constants
    float a[KT], na[KT];
    #pragma unroll
    for (int kk = 0; kk < KT; kk++) {
        if (kk < kcnt) {
            const int k = kbase + kk;
            const float av = fmaxf(__ldg(alpha + k), 0.0f) * 1.4426950408889634f;
            a[kk]  = av;
            na[kk] = -av * (4.0f * (float)k);
        } else { a[kk] = 0.0f; na[kk] = 0.0f; }
    }

    float acc[KT][BT];
    #pragma unroll
    for (int kk = 0; kk < KT; kk++)
        #pragma unroll
        for (int bi = 0; bi < BT; bi++) acc[kk][bi] = 0.0f;

    const size_t bstr = (size_t)LN * DN;
    const size_t dofs = (size_t)b0 * bstr + d;

    // double buffers (inputs + small weights); wt float4 is single-buffered
    float xB[2][BT], tB[2][BT], mB[2][BT], dtB[2][BT];
    float wvB[2][KT], btB[2][KT];

    // ---- prologue: load step l0 into buffer 0 ----
    #pragma unroll
    for (int bi = 0; bi < BT; bi++) {
        const size_t o = dofs + (size_t)bi * bstr + (size_t)l0 * DN;
        xB[0][bi]  = __ldg(X  + o);
        tB[0][bi]  = __ldg(T  + o);
        mB[0][bi]  = __ldg(M  + o);
        dtB[0][bi] = __ldg(DT + o);
    }
    #pragma unroll
    for (int kk = 0; kk < KT; kk++) {
        if (kk < kcnt) {
            const size_t woff = ((size_t)(kbase + kk) * LN + l0) * DN + d;
            wvB[0][kk] = __ldg(w_v + woff);
            btB[0][kk] = __ldg(b_t + woff);
        }
    }

    #pragma unroll
    for (int li = 0; li < LC; li++) {
        const int cur = li & 1;
        const int nxt = cur ^ 1;
        const int l   = l0 + li;

        // ---- issue next step's loads FIRST (drain under this step's compute) ----
        if (li + 1 < LC) {
            const int ln = l + 1;
            #pragma unroll
            for (int bi = 0; bi < BT; bi++) {
                const size_t o = dofs + (size_t)bi * bstr + (size_t)ln * DN;
                xB[nxt][bi]  = __ldg(X  + o);
                tB[nxt][bi]  = __ldg(T  + o);
                mB[nxt][bi]  = __ldg(M  + o);
                dtB[nxt][bi] = __ldg(DT + o);
            }
            #pragma unroll
            for (int kk = 0; kk < KT; kk++) {
                if (kk < kcnt) {
                    const size_t woff = ((size_t)(kbase + kk) * LN + ln) * DN + d;
                    wvB[nxt][kk] = __ldg(w_v + woff);
                    btB[nxt][kk] = __ldg(b_t + woff);
                }
            }
        }

        // ---- wt batch for current step (self-hidden: consumed progressively) ----
        float4 wt[KT];
        #pragma unroll
        for (int kk = 0; kk < KT; kk++) {
            if (kk < kcnt) {
                const size_t woff = ((size_t)(kbase + kk) * LN + l) * DN + d;
                wt[kk] = __ldg(reinterpret_cast<const float4*>(w_t) + woff);
            }
        }

        float rx[BT];
        #pragma unroll
        for (int bi = 0; bi < BT; bi++) rx[bi] = fmaxf(xB[cur][bi], 0.0f);

        // ---- compute from buffer cur ----
        #pragma unroll
        for (int kk = 0; kk < KT; kk++) {
            if (kk < kcnt) {
                const float ak = a[kk], nak = na[kk];
                const float4 w = wt[kk];
                const float wvk = wvB[cur][kk];
                const float btk = 4.0f * btB[cur][kk];

                #pragma unroll
                for (int bi = 0; bi < BT; bi++) {
                    const float ww = fmaf(tB[cur][bi], ak, nak);
                    const float e  = ex2f(-fabsf(ww));       // 2^(-|w|)
                    const float in = e * rx[bi];
                    const float s  = fmaf(w.x, xB[cur][bi],
                                     fmaf(w.y, dtB[cur][bi],
                                     fmaf(w.z, in,
                                     fmaf(w.w, mB[cur][bi], btk))));
                    acc[kk][bi] = fmaf(wvk, fmaxf(s, 0.0f), acc[kk][bi]);
                }
            }
        }
    }

    // coalesced fp32 reductions into the L2-resident accumulator
    #pragma unroll
    for (int kk = 0; kk < KT; kk++) {
        if (kk < kcnt) {
            #pragma unroll
            for (int bi = 0; bi < BT; bi++) {
                atomicAdd(&g_accum[((size_t)(b0 + bi) * KREF + (kbase + kk)) * DN + d],
                          acc[kk][bi]);
            }
        }
    }
}

// bias + relu epilogue; one scalar per thread (208 blocks). Re-zeroes accumulator.
__global__ __launch_bounds__(256)
void alnn_biaszero(const float* __restrict__ b_v, float* __restrict__ out)
{
    const int g = blockIdx.x * 256 + threadIdx.x;   // over BKD = 53248
    if (g >= BKD) return;
    const int d  = g & 63;
    const int k  = (g >> 6) % KREF;

    const float s  = g_accum[g];
    const float bv = __ldg(b_v + k * DN + d);
    out[g] = fmaxf(fmaf(200.f, bv, s), 0.f);
    g_accum[g] = 0.f;                               // ready for next call
}

extern "C" void kernel_launch(void* const* d_in, const int* in_sizes, int n_in,
                              void* d_out, int out_size)
{
    // metadata order: X, T, M, DT, alpha, w_v, w_t, b_v, b_t
    const float* X     = (const float*)d_in[0];
    const float* T     = (const float*)d_in[1];
    const float* M     = (const float*)d_in[2];
    const float* DT    = (const float*)d_in[3];
    const float* alpha = (const float*)d_in[4];
    const float* w_v   = (const float*)d_in[5];
    const float* w_t   = (const float*)d_in[6];
    const float* b_v   = (const float*)d_in[7];
    const float* b_t   = (const float*)d_in[8];
    float* out = (float*)d_out;

    dim3 grid(NCH, NBT);
    alnn_main<<<grid, 128>>>(X, T, M, DT, alpha, w_v, w_t, b_t);
    alnn_biaszero<<<(BKD + 255) / 256, 256>>>(b_v, out);
}